// round 2
// baseline (speedup 1.0000x reference)
#include <cuda_runtime.h>

#define N_NODES 8192
#define N_EDGES 131072
#define FEAT    512
#define HID     256
#define OUTD    1792     // (2^(K+1)-1)*HID
#define NGRAPH  64
#define WORDS   256      // 8192 / 32 bits
#define MAXNZ   4096     // per-row 2-hop cap (realistic max ~1600)

// ---------------- device scratch (no allocations allowed) ----------------
__device__ unsigned g_Abit [N_NODES * WORDS];   // raw binarized adjacency (8 MB)
__device__ unsigned g_A2bit[N_NODES * WORDS];   // strict 2-hop adjacency  (8 MB)
__device__ int      g_selfcnt[N_NODES];
__device__ float    g_dinv1[N_NODES];
__device__ float    g_dinv2[N_NODES];
__device__ float    g_h[(size_t)N_NODES * OUTD]; // h_node: [r | rs1 | rs2] (56 MB)
__device__ float    g_pool[NGRAPH * OUTD];
__device__ int      g_gcnt[NGRAPH];
__device__ int      g_e64, g_b64;               // int64-layout flags

// int32/int64 layout auto-detect helper
__device__ __forceinline__ int geti(const void* p, int i, int is64) {
    return is64 ? (int)((const long long*)p)[i] : ((const int*)p)[i];
}

// ---------------- dtype detection ----------------
// If buffer holds int64 little-endian values in [0, 2^31), every odd 32-bit
// word (high half) is 0. If it holds int32 values, odd words are data and are
// nonzero with overwhelming probability (edges: uniform [0,8192);
// batch: sorted [0,64) sampled over ALL elements).
__global__ void k_detect(const int* __restrict__ w, int nwords, int* flag) {
    __shared__ int s_any;
    if (threadIdx.x == 0) s_any = 0;
    __syncthreads();
    int any = 0;
    for (int k = 1 + 2 * (int)threadIdx.x; k < nwords; k += 2 * (int)blockDim.x)
        any |= w[k];
    if (any) atomicOr(&s_any, 1);
    __syncthreads();
    if (threadIdx.x == 0) *flag = s_any ? 0 : 1;   // 1 => int64 layout
}

// ---------------- build raw adjacency bitmask ----------------
__global__ void k_edges(const void* __restrict__ e, const int* __restrict__ e64flag) {
    int i = blockIdx.x * blockDim.x + threadIdx.x;
    if (i >= N_EDGES) return;
    int is64 = *e64flag;
    int r = geti(e, i, is64);
    int c = geti(e, N_EDGES + i, is64);
    atomicOr(&g_Abit[r * WORDS + (c >> 5)], 1u << (c & 31));
    if (r == c) atomicAdd(&g_selfcnt[r], 1);
}

// ---------------- A2 = (A@A > 0) & ~A & ~I ; degrees -> dinv ----------------
__global__ __launch_bounds__(256) void k_a2() {
    int i = blockIdx.x, t = threadIdx.x;
    __shared__ int s_pc[256];
    __shared__ int s_nbr[128];
    __shared__ int s_r1[256], s_r2[256];

    unsigned w = g_Abit[i * WORDS + t];
    int pc = __popc(w);
    s_pc[t] = pc;
    __syncthreads();
    // inclusive scan over per-word popcounts (deterministic ordered extraction)
    for (int off = 1; off < 256; off <<= 1) {
        int v = (t >= off) ? s_pc[t - off] : 0;
        __syncthreads();
        s_pc[t] += v;
        __syncthreads();
    }
    int o = s_pc[t] - pc;
    unsigned tmp = w;
    while (tmp) {
        int b = __ffs(tmp) - 1; tmp &= tmp - 1;
        if (o < 128) s_nbr[o] = t * 32 + b;
        o++;
    }
    int cnt = min(s_pc[255], 128);
    __syncthreads();

    // OR neighbor rows (word t of each) -> 2-hop reachability word
    unsigned acc = 0;
    for (int n = 0; n < cnt; n++)
        acc |= g_Abit[s_nbr[n] * WORDS + t];

    unsigned dm = (t == (i >> 5)) ? (1u << (i & 31)) : 0u;
    unsigned a2 = acc & ~w & ~dm;
    g_A2bit[i * WORDS + t] = a2;

    // A1 diagonal rule: (A - I) > 0 keeps diag only if >= 2 self-loops
    unsigned a1 = w;
    if (dm && (w & dm) && g_selfcnt[i] < 2) a1 &= ~dm;

    s_r1[t] = __popc(a1);
    s_r2[t] = __popc(a2);
    __syncthreads();
    for (int off = 128; off > 0; off >>= 1) {
        if (t < off) { s_r1[t] += s_r1[t + off]; s_r2[t] += s_r2[t + off]; }
        __syncthreads();
    }
    if (t == 0) {
        g_dinv1[i] = s_r1[0] > 0 ? rsqrtf((float)s_r1[0]) : 0.f;
        g_dinv2[i] = s_r2[0] > 0 ? rsqrtf((float)s_r2[0]) : 0.f;
    }
}

// ---------------- embed: r = relu(x @ w_embed) -> g_h[:, 0:256] ----------------
// 64x64 tile, BK=16, 256 threads, 4x4 per thread.
__global__ __launch_bounds__(256) void k_embed(const float* __restrict__ X,
                                               const float* __restrict__ W) {
    __shared__ float As[16][64 + 4];
    __shared__ float Bs[16][64 + 4];
    int bm = blockIdx.x * 64;
    int bn = blockIdx.y * 64;
    int tid = threadIdx.x;
    int tr = tid >> 4, tc = tid & 15;
    float acc[4][4] = {};
    for (int k0 = 0; k0 < FEAT; k0 += 16) {
        {   // A tile: 64 rows x 16 k
            int m  = tid >> 2;
            int kg = (tid & 3) * 4;
            float4 v = *(const float4*)(X + (size_t)(bm + m) * FEAT + k0 + kg);
            As[kg + 0][m] = v.x; As[kg + 1][m] = v.y;
            As[kg + 2][m] = v.z; As[kg + 3][m] = v.w;
        }
        {   // B tile: 16 k x 64 cols
            int k  = tid >> 4;
            int ng = (tid & 15) * 4;
            float4 v = *(const float4*)(W + (size_t)(k0 + k) * HID + bn + ng);
            Bs[k][ng + 0] = v.x; Bs[k][ng + 1] = v.y;
            Bs[k][ng + 2] = v.z; Bs[k][ng + 3] = v.w;
        }
        __syncthreads();
#pragma unroll
        for (int kk = 0; kk < 16; kk++) {
            float a[4], b[4];
#pragma unroll
            for (int q = 0; q < 4; q++) a[q] = As[kk][tr * 4 + q];
#pragma unroll
            for (int q = 0; q < 4; q++) b[q] = Bs[kk][tc * 4 + q];
#pragma unroll
            for (int p = 0; p < 4; p++)
#pragma unroll
                for (int q = 0; q < 4; q++)
                    acc[p][q] += a[p] * b[q];
        }
        __syncthreads();
    }
#pragma unroll
    for (int p = 0; p < 4; p++)
#pragma unroll
        for (int q = 0; q < 4; q++) {
            float v = acc[p][q];
            g_h[(size_t)(bm + tr * 4 + p) * OUTD + bn + tc * 4 + q] = v > 0.f ? v : 0.f;
        }
}

// ---------------- SpMM from bitmask: out = relu(dinv_i * sum_j dinv_j * in_j) ----------------
__global__ __launch_bounds__(256) void k_spmm(const unsigned* __restrict__ bits,
                                              const float* __restrict__ dinv,
                                              int in_off, int C, int out_off, int fixdiag) {
    int i = blockIdx.x, t = threadIdx.x;
    __shared__ int   s_pc[256];
    __shared__ int   s_idx[MAXNZ];
    __shared__ float s_val[MAXNZ];

    unsigned w = bits[i * WORDS + t];
    if (fixdiag && t == (i >> 5)) {
        unsigned dm = 1u << (i & 31);
        if ((w & dm) && g_selfcnt[i] < 2) w &= ~dm;
    }
    int pc = __popc(w);
    s_pc[t] = pc;
    __syncthreads();
    for (int off = 1; off < 256; off <<= 1) {
        int v = (t >= off) ? s_pc[t - off] : 0;
        __syncthreads();
        s_pc[t] += v;
        __syncthreads();
    }
    int o = s_pc[t] - pc;
    unsigned tmp = w;
    while (tmp) {
        int b = __ffs(tmp) - 1; tmp &= tmp - 1;
        if (o < MAXNZ) {
            int j = t * 32 + b;
            s_idx[o] = j;
            s_val[o] = dinv[j];
        }
        o++;
    }
    int cnt = min(s_pc[255], MAXNZ);
    __syncthreads();

    float di = dinv[i];
    for (int f = t; f < C; f += 256) {
        float a0 = 0.f, a1 = 0.f, a2 = 0.f, a3 = 0.f;
        int n = 0;
        for (; n + 3 < cnt; n += 4) {   // 4 independent accumulators -> MLP=4
            a0 += s_val[n + 0] * g_h[(size_t)s_idx[n + 0] * OUTD + in_off + f];
            a1 += s_val[n + 1] * g_h[(size_t)s_idx[n + 1] * OUTD + in_off + f];
            a2 += s_val[n + 2] * g_h[(size_t)s_idx[n + 2] * OUTD + in_off + f];
            a3 += s_val[n + 3] * g_h[(size_t)s_idx[n + 3] * OUTD + in_off + f];
        }
        for (; n < cnt; n++)
            a0 += s_val[n] * g_h[(size_t)s_idx[n] * OUTD + in_off + f];
        float v = di * ((a0 + a1) + (a2 + a3));
        g_h[(size_t)i * OUTD + out_off + f] = v > 0.f ? v : 0.f;
    }
}

// ---------------- graph sizes ----------------
__global__ void k_count(const void* __restrict__ batch, const int* __restrict__ b64flag) {
    int i = blockIdx.x * blockDim.x + threadIdx.x;
    if (i < N_NODES) atomicAdd(&g_gcnt[geti(batch, i, *b64flag)], 1);
}

// ---------------- segment-sum pool (batch is sorted) ----------------
__global__ __launch_bounds__(256) void k_pool(const void* __restrict__ batch,
                                              const int* __restrict__ b64flag) {
    int is64 = *b64flag;
    int n0 = blockIdx.x * 128;          // 64 node-blocks of 128
    int c  = blockIdx.y * 256 + threadIdx.x;   // 7 col-blocks of 256
    float acc = 0.f;
    int cur = geti(batch, n0, is64);
    for (int n = n0; n < n0 + 128; n++) {
        int b = geti(batch, n, is64);
        if (b != cur) {
            atomicAdd(&g_pool[cur * OUTD + c], acc);
            acc = 0.f; cur = b;
        }
        acc += g_h[(size_t)n * OUTD + c];
    }
    atomicAdd(&g_pool[cur * OUTD + c], acc);
}

// ---------------- final: (pool/cnt) @ W_out + b_out ; tail = loss = 0 ----------------
__global__ __launch_bounds__(256) void k_out(const float* __restrict__ Wout,
                                             const float* __restrict__ bout,
                                             float* __restrict__ out, int out_size) {
    int g = blockIdx.x, h = threadIdx.x;
    __shared__ float sg[OUTD];
    float inv = 1.0f / fmaxf((float)g_gcnt[g], 1.0f);
    for (int k = h; k < OUTD; k += 256)
        sg[k] = g_pool[g * OUTD + k] * inv;
    __syncthreads();
    float acc = bout[h];
    for (int k = 0; k < OUTD; k++)
        acc += sg[k] * Wout[(size_t)k * HID + h];
    int oi = g * HID + h;
    if (oi < out_size) out[oi] = acc;
    if (g == 0) {   // zero additional_loss / any tail
        for (int idx = NGRAPH * HID + h; idx < out_size; idx += 256)
            out[idx] = 0.f;
    }
}

// ---------------- launcher ----------------
extern "C" void kernel_launch(void* const* d_in, const int* in_sizes, int n_in,
                              void* d_out, int out_size) {
    const float* x       = (const float*)d_in[0];
    const void*  e       = d_in[1];
    const void*  batch   = d_in[2];
    const float* w_embed = (const float*)d_in[3];
    const float* W_out   = (const float*)d_in[4];
    const float* b_out   = (const float*)d_in[5];
    float* out = (float*)d_out;

    void *pA, *pA2, *pSelf, *pPool, *pGcnt, *pD1, *pD2, *pE64, *pB64;
    cudaGetSymbolAddress(&pA,    g_Abit);
    cudaGetSymbolAddress(&pA2,   g_A2bit);
    cudaGetSymbolAddress(&pSelf, g_selfcnt);
    cudaGetSymbolAddress(&pPool, g_pool);
    cudaGetSymbolAddress(&pGcnt, g_gcnt);
    cudaGetSymbolAddress(&pD1,   g_dinv1);
    cudaGetSymbolAddress(&pD2,   g_dinv2);
    cudaGetSymbolAddress(&pE64,  g_e64);
    cudaGetSymbolAddress(&pB64,  g_b64);

    cudaMemsetAsync(pA,    0, sizeof(unsigned) * N_NODES * WORDS);
    cudaMemsetAsync(pSelf, 0, sizeof(int)   * N_NODES);
    cudaMemsetAsync(pPool, 0, sizeof(float) * NGRAPH * OUTD);
    cudaMemsetAsync(pGcnt, 0, sizeof(int)   * NGRAPH);

    // dtype layout detection (int32 vs int64)
    k_detect<<<1, 128>>>((const int*)e,     2 * N_EDGES, (int*)pE64);
    k_detect<<<1, 128>>>((const int*)batch, N_NODES,     (int*)pB64);

    k_edges<<<(N_EDGES + 255) / 256, 256>>>(e, (const int*)pE64);
    k_embed<<<dim3(N_NODES / 64, HID / 64), 256>>>(x, w_embed);
    k_a2<<<N_NODES, 256>>>();

    // hop 1: in = cols [0,256)
    k_spmm<<<N_NODES, 256>>>((const unsigned*)pA,  (const float*)pD1, 0,   HID,     HID,     1);
    k_spmm<<<N_NODES, 256>>>((const unsigned*)pA2, (const float*)pD2, 0,   HID,     2 * HID, 0);
    // hop 2: in = cols [256,768)
    k_spmm<<<N_NODES, 256>>>((const unsigned*)pA,  (const float*)pD1, HID, 2 * HID, 3 * HID, 1);
    k_spmm<<<N_NODES, 256>>>((const unsigned*)pA2, (const float*)pD2, HID, 2 * HID, 5 * HID, 0);

    k_count<<<(N_NODES + 255) / 256, 256>>>(batch, (const int*)pB64);
    k_pool<<<dim3(N_NODES / 128, OUTD / 256), 256>>>(batch, (const int*)pB64);
    k_out<<<NGRAPH, HID>>>(W_out, b_out, out, out_size);
}